// round 1
// baseline (speedup 1.0000x reference)
#include <cuda_runtime.h>
#include <cuda_bf16.h>

// DilateAttention: B=4, d=384 (12 heads x 32), H=W=64, 3x3 kernel, dilation 2, zero pad 2.
// q,k,v: [B, 384, 64, 64] f32 (channel-major). out: [B, 64, 64, 384] f32.

#define Bc     4
#define Dc     384
#define NH     12
#define HD     32
#define HH     64
#define WW     64
#define TW     32
#define TH     8
#define RR     (TH + 4)          // 12 rows incl. halo
#define CC     (TW + 4)          // 36 cols incl. halo
#define TILE_ELEMS (HD * RR * CC) // 13824
#define SCALE  0.17677669529663689f  // 32^-0.5

__global__ __launch_bounds__(256, 2)
void dilate_attn_kernel(const float* __restrict__ q,
                        const float* __restrict__ k,
                        const float* __restrict__ v,
                        float* __restrict__ out)
{
    extern __shared__ float smem[];
    float* ks = smem;                  // [HD][RR][CC]
    float* vs = smem + TILE_ELEMS;     // [HD][RR][CC]

    const int tx = threadIdx.x;        // 0..31  (w within tile)
    const int ty = threadIdx.y;        // 0..7   (h within tile)
    const int tid = ty * 32 + tx;

    const int w0 = blockIdx.x * TW;
    const int h0 = blockIdx.y * TH;
    const int bh = blockIdx.z;         // 0..47
    const int b    = bh / NH;
    const int head = bh - b * NH;

    // base offset of channel 0 of this (batch, head) in q/k/v
    const size_t base = ((size_t)b * Dc + (size_t)head * HD) * (HH * WW);

    // ---- stage k and v halo tiles into shared memory (zero-fill OOB) ----
    #pragma unroll 1
    for (int idx = tid; idx < TILE_ELEMS; idx += 256) {
        const int c   = idx / (RR * CC);
        const int rem = idx - c * (RR * CC);
        const int r   = rem / CC;
        const int cc  = rem - r * CC;
        const int gh  = h0 - 2 + r;
        const int gw  = w0 - 2 + cc;
        float kv = 0.0f, vv = 0.0f;
        if ((unsigned)gh < HH && (unsigned)gw < WW) {
            const size_t off = base + (size_t)c * (HH * WW) + gh * WW + gw;
            kv = __ldg(k + off);
            vv = __ldg(v + off);
        }
        ks[idx] = kv;
        vs[idx] = vv;
    }

    // ---- q for this thread's pixel into registers (coalesced per channel) ----
    const int h = h0 + ty;
    const int w = w0 + tx;
    float qr[HD];
    {
        const float* qp = q + base + h * WW + w;
        #pragma unroll
        for (int c = 0; c < HD; c++)
            qr[c] = __ldg(qp + (size_t)c * (HH * WW));
    }

    __syncthreads();

    // ---- attention logits over the 9 dilated neighbors ----
    float lg[9];
    #pragma unroll
    for (int kp = 0; kp < 9; kp++) {
        const int di = kp / 3;          // 0,1,2 -> row offset 2*di - 2
        const int dj = kp - di * 3;
        const int r  = ty + 2 * di;     // index into halo tile
        const int cc = tx + 2 * dj;
        float dot = 0.0f;
        #pragma unroll
        for (int c = 0; c < HD; c++)
            dot = fmaf(qr[c], ks[(c * RR + r) * CC + cc], dot);
        lg[kp] = dot * SCALE;           // OOB neighbors: k==0 in smem -> logit 0 (matches zero-pad)
    }

    // ---- softmax over 9 ----
    float m = lg[0];
    #pragma unroll
    for (int kp = 1; kp < 9; kp++) m = fmaxf(m, lg[kp]);
    float p[9];
    float s = 0.0f;
    #pragma unroll
    for (int kp = 0; kp < 9; kp++) { p[kp] = __expf(lg[kp] - m); s += p[kp]; }
    const float inv = __fdividef(1.0f, s);

    // ---- weighted sum of v (unnormalized, scale once at end) ----
    float acc[HD];
    #pragma unroll
    for (int c = 0; c < HD; c++) acc[c] = 0.0f;
    #pragma unroll
    for (int kp = 0; kp < 9; kp++) {
        const int di = kp / 3;
        const int dj = kp - di * 3;
        const int r  = ty + 2 * di;
        const int cc = tx + 2 * dj;
        const float pw = p[kp];
        #pragma unroll
        for (int c = 0; c < HD; c++)
            acc[c] = fmaf(pw, vs[(c * RR + r) * CC + cc], acc[c]);
    }

    // ---- transpose through smem (reuse ks) for coalesced 128B output stores ----
    __syncthreads();   // everyone done reading ks/vs before overwrite
    // layout: ts[pixel][c] with stride 33 to avoid bank conflicts
    float* ts = ks;    // needs 256*33 floats = 8448 < TILE_ELEMS
    #pragma unroll
    for (int c = 0; c < HD; c++)
        ts[(ty * 32 + tx) * 33 + c] = acc[c] * inv;
    __syncwarp();      // warp ty only reads pixels written by warp ty

    // out[((b*64 + h)*64 + w)*384 + head*32 + c]; lane = channel now
    const size_t obase = (((size_t)b * HH + h) * WW + w0) * Dc + (size_t)head * HD;
    #pragma unroll 4
    for (int pp = 0; pp < 32; pp++) {
        out[obase + (size_t)pp * Dc + tx] = ts[(ty * 32 + pp) * 33 + tx];
    }
}

extern "C" void kernel_launch(void* const* d_in, const int* in_sizes, int n_in,
                              void* d_out, int out_size)
{
    const float* q = (const float*)d_in[0];
    const float* k = (const float*)d_in[1];
    const float* v = (const float*)d_in[2];
    float* out = (float*)d_out;

    const int smem_bytes = 2 * TILE_ELEMS * sizeof(float); // 110592
    cudaFuncSetAttribute(dilate_attn_kernel,
                         cudaFuncAttributeMaxDynamicSharedMemorySize, smem_bytes);

    dim3 block(32, 8, 1);
    dim3 grid(WW / TW, HH / TH, Bc * NH);   // (2, 8, 48)
    dilate_attn_kernel<<<grid, block, smem_bytes>>>(q, k, v, out);
}

// round 3
// speedup vs baseline: 2.1894x; 2.1894x over previous
#include <cuda_runtime.h>
#include <cstdint>

// DilateAttention: B=4, d=384 (12 heads x 32), H=W=64, 3x3 kernel, dilation 2, zero pad 2.
// q,k,v: [B, 384, 64, 64] f32. out: [B, 64, 64, 384] f32.

#define NH  12
#define HD  32
#define HH  64
#define WW  64
#define TH  4
#define RR  (TH + 4)            // 8 rows incl. halo
#define CC  68                  // 64 cols + 2 zero-pad each side
#define TILE_FLOATS (HD * RR * CC)   // 17408
#define SMEM_FLOATS (TILE_FLOATS + 4)
#define SCALE 0.17677669529663689f   // 32^-0.5

__device__ __forceinline__ void cp_async16(uint32_t saddr, const void* gptr) {
    asm volatile("cp.async.cg.shared.global [%0], [%1], 16;\n" :: "r"(saddr), "l"(gptr));
}
__device__ __forceinline__ void cp_commit_wait() {
    asm volatile("cp.async.commit_group;\ncp.async.wait_group 0;\n" ::: "memory");
}

__global__ __launch_bounds__(256, 3)
void dilate_attn_kernel(const float* __restrict__ q,
                        const float* __restrict__ k,
                        const float* __restrict__ v,
                        float* __restrict__ out)
{
    extern __shared__ float smem[];
    // tile[c][r][cc] at smem+2: interior (cc=2) byte addr = row*272 + 16 -> 16B aligned every row
    float* tile = smem + 2;

    const int tx  = threadIdx.x;       // 0..63 = w
    const int ty  = threadIdx.y;       // 0..3
    const int tid = ty * 64 + tx;

    const int h0   = blockIdx.x * TH;
    const int bh   = blockIdx.y;       // 0..47
    const int b    = bh / NH;
    const int head = bh - b * NH;
    const size_t base = ((size_t)b * 384 + (size_t)head * HD) * (HH * WW);

    // ---- staging assignment: one halo row per thread (32ch x 8rows = 256 rows) ----
    const int sc = tid >> 3;           // channel 0..31
    const int sr = tid & 7;            // halo row 0..7
    const int gh = h0 - 2 + sr;
    const int rowoff = (sc * RR + sr) * CC;
    const bool inb = (unsigned)gh < HH;
    const float* gk = k + base + (size_t)sc * (HH * WW) + gh * WW;
    const float* gv = v + base + (size_t)sc * (HH * WW) + gh * WW;
    const uint32_t s_int = (uint32_t)__cvta_generic_to_shared(&tile[rowoff + 2]);

    // ---- phase K: stage k tile (full 64-wide aligned rows via cp.async) ----
    if (inb) {
        #pragma unroll
        for (int j = 0; j < 16; j++) cp_async16(s_int + j * 16, gk + j * 4);
        // zero pads (persist for V phase too)
        tile[rowoff + 0] = 0.f; tile[rowoff + 1] = 0.f;
        tile[rowoff + 66] = 0.f; tile[rowoff + 67] = 0.f;
    } else {
        #pragma unroll
        for (int j = 0; j < CC; j++) tile[rowoff + j] = 0.f;
    }

    // q into registers while cp.async streams (coalesced: lane = consecutive w)
    const int h = h0 + ty;
    float qr[HD];
    {
        const float* qp = q + base + h * WW + tx;
        #pragma unroll
        for (int c = 0; c < HD; c++) qr[c] = qp[(size_t)c * (HH * WW)];
    }

    cp_commit_wait();
    __syncthreads();

    // ---- logits over 9 dilated neighbors ----
    float lg[9];
    #pragma unroll
    for (int kp = 0; kp < 9; kp++) {
        const int di = kp / 3;
        const int dj = kp - di * 3;
        const int r  = ty + 2 * di;        // 0..7
        const int cc = tx + 2 * dj;        // 0..67
        const float* kr = &tile[r * CC + cc];
        float d0 = 0.f, d1 = 0.f;
        #pragma unroll
        for (int c = 0; c < HD; c += 2) {
            d0 = fmaf(qr[c],     kr[(c)     * (RR * CC)], d0);
            d1 = fmaf(qr[c + 1], kr[(c + 1) * (RR * CC)], d1);
        }
        lg[kp] = (d0 + d1) * SCALE;        // OOB neighbor -> k==0 -> logit 0 (matches zero-pad)
    }

    // ---- softmax over 9 ----
    float m = lg[0];
    #pragma unroll
    for (int kp = 1; kp < 9; kp++) m = fmaxf(m, lg[kp]);
    float p[9];
    float s = 0.f;
    #pragma unroll
    for (int kp = 0; kp < 9; kp++) { p[kp] = __expf(lg[kp] - m); s += p[kp]; }
    const float inv = __fdividef(1.f, s);

    // ---- phase V: restage same buffer with v (pads/OOB rows already zero) ----
    __syncthreads();                       // everyone done reading k
    if (inb) {
        #pragma unroll
        for (int j = 0; j < 16; j++) cp_async16(s_int + j * 16, gv + j * 4);
    }
    cp_commit_wait();
    __syncthreads();

    // ---- weighted sum of v ----
    float acc[HD];
    #pragma unroll
    for (int c = 0; c < HD; c++) acc[c] = 0.f;
    #pragma unroll
    for (int kp = 0; kp < 9; kp++) {
        const int di = kp / 3;
        const int dj = kp - di * 3;
        const int r  = ty + 2 * di;
        const int cc = tx + 2 * dj;
        const float pw = p[kp];
        const float* vr = &tile[r * CC + cc];
        #pragma unroll
        for (int c = 0; c < HD; c++)
            acc[c] = fmaf(pw, vr[c * (RR * CC)], acc[c]);
    }

    // ---- transpose through smem for coalesced 128B output stores ----
    __syncthreads();                       // done reading v before overwrite
    float* ts = smem;                      // 256*33 = 8448 floats < SMEM_FLOATS
    #pragma unroll
    for (int c = 0; c < HD; c++)
        ts[tid * 33 + c] = acc[c] * inv;
    __syncwarp();                          // each warp reads only its own 32 pixels

    const int lane  = tid & 31;            // becomes channel
    const int wbase = tid & ~31;
    #pragma unroll 4
    for (int pp = 0; pp < 32; pp++) {
        const int pid = wbase + pp;
        const int h2 = h0 + (pid >> 6);
        const int w2 = pid & 63;
        out[(((size_t)b * HH + h2) * WW + w2) * 384 + (size_t)head * HD + lane]
            = ts[pid * 33 + lane];
    }
}

extern "C" void kernel_launch(void* const* d_in, const int* in_sizes, int n_in,
                              void* d_out, int out_size)
{
    const float* q = (const float*)d_in[0];
    const float* k = (const float*)d_in[1];
    const float* v = (const float*)d_in[2];
    float* out = (float*)d_out;

    const int smem_bytes = SMEM_FLOATS * sizeof(float);   // 69648
    cudaFuncSetAttribute(dilate_attn_kernel,
                         cudaFuncAttributeMaxDynamicSharedMemorySize, smem_bytes);

    dim3 block(64, 4, 1);
    dim3 grid(HH / TH, 4 * NH, 1);        // (16, 48)
    dilate_attn_kernel<<<grid, block, smem_bytes>>>(q, k, v, out);
}